// round 3
// baseline (speedup 1.0000x reference)
#include <cuda_runtime.h>
#include <math.h>
#include <stdint.h>

// Problem constants (fixed by the dataset)
#define NN 100000       // nodes
#define NE 600000       // edges
// IN = OUT = ED = 128, H = 2, C = 64, MSG = 64, T = 64

// ---------------------------------------------------------------------------
// Scratch (device globals; no allocation allowed)
// ---------------------------------------------------------------------------
__device__ float    g_q[(size_t)NN * 128];
__device__ float    g_k[(size_t)NN * 128];
__device__ float    g_v[(size_t)NN * 128];
__device__ float    g_e[(size_t)NE * 128];
__device__ float    g_ex[(size_t)NE * 2];      // alpha, then exp(alpha - amax)
__device__ unsigned g_amax[(size_t)NN * 2];    // order-encoded float max keys
__device__ float    g_denom[(size_t)NN * 2];

// ---------------------------------------------------------------------------
// Helpers
// ---------------------------------------------------------------------------
typedef unsigned long long ull;

__device__ __forceinline__ ull pk2(float a) {
    ull r;
    asm("mov.b64 %0, {%1, %1};" : "=l"(r) : "f"(a));
    return r;
}
__device__ __forceinline__ void fma2(ull &d, ull a, ull b) {
    asm("fma.rn.f32x2 %0, %1, %2, %0;" : "+l"(d) : "l"(a), "l"(b));
}
__device__ __forceinline__ float2 up2(ull v) {
    float2 f;
    asm("mov.b64 {%0, %1}, %2;" : "=f"(f.x), "=f"(f.y) : "l"(v));
    return f;
}

// Total-order encoding of float for unsigned atomicMax.
// All finite floats map to keys > 0, so initializing keys to 0 is safe.
__device__ __forceinline__ unsigned fkey(float f) {
    unsigned u = __float_as_uint(f);
    return (u & 0x80000000u) ? ~u : (u | 0x80000000u);
}
__device__ __forceinline__ float funkey(unsigned k) {
    return (k & 0x80000000u) ? __uint_as_float(k & 0x7fffffffu)
                             : __uint_as_float(~k);
}

// Accurate cos(rel_t * w + b) matching the reference's fp32 argument:
//   - argument computed with exact fp32 mul then add (no FMA contraction)
//   - double-precision range reduction by 2*pi (robust under fast-math)
//   - cosf on the reduced range [-pi, pi]
__device__ __forceinline__ float cos_arg(float rt, float w, float b) {
    float arg = __fadd_rn(__fmul_rn(rt, w), b);
    double xd = (double)arg;
    double kd = rint(xd * 0.15915494309189535);        // 1 / (2*pi)
    float  r  = (float)(xd - kd * 6.283185307179586);  // in [-pi, pi]
    return cosf(r);
}

// ---------------------------------------------------------------------------
// K0: init segment-softmax scratch
// ---------------------------------------------------------------------------
__global__ void init_kernel() {
    int i = blockIdx.x * blockDim.x + threadIdx.x;
    if (i < NN * 2) {
        g_amax[i]  = 0u;     // below fkey of any finite float
        g_denom[i] = 0.0f;
    }
}

// ---------------------------------------------------------------------------
// K1: node projections.  C[128 rows x 128 cols] = x_tile @ W + bias.
// gridDim.y selects the matrix: 0->q, 1->k, 2->v, 3->skip (written to out).
// Whole K=128 is resident in smem: load once, no pipelining needed.
// ---------------------------------------------------------------------------
#define PROJ_SMEM_FLOATS (128 * 128 * 2 + 128)
#define PROJ_SMEM_BYTES  (PROJ_SMEM_FLOATS * 4)

__global__ void __launch_bounds__(256, 1) proj_kernel(
    const float* __restrict__ x,
    const float* __restrict__ Wq, const float* __restrict__ bq,
    const float* __restrict__ Wk, const float* __restrict__ bk,
    const float* __restrict__ Wv, const float* __restrict__ bv,
    const float* __restrict__ Ws, const float* __restrict__ bs,
    float* __restrict__ out)
{
    extern __shared__ float sm[];
    float* sA    = sm;                 // x tile   [m][k]  128x128
    float* sB    = sm + 128 * 128;     // W tile   [k][n]  128x128
    float* sbias = sB + 128 * 128;     // bias     [n]     128

    const int tid   = threadIdx.x;
    const int which = blockIdx.y;
    const float* W;  const float* bias;  float* dst;
    switch (which) {
        case 0:  W = Wq; bias = bq; dst = g_q; break;
        case 1:  W = Wk; bias = bk; dst = g_k; break;
        case 2:  W = Wv; bias = bv; dst = g_v; break;
        default: W = Ws; bias = bs; dst = out; break;
    }

    const int row0 = blockIdx.x * 128;

    // Load W (coalesced float4, conflict-free contiguous STS.128)
    for (int idx = tid; idx < 128 * 32; idx += 256) {
        int k = idx >> 5, nc = idx & 31;
        *(float4*)&sB[k * 128 + nc * 4] = *(const float4*)&W[k * 128 + nc * 4];
    }
    if (tid < 128) sbias[tid] = bias[tid];
    // Load x tile (zero-pad rows past N)
    for (int idx = tid; idx < 128 * 32; idx += 256) {
        int m = idx >> 5, kc = idx & 31;
        int row = row0 + m;
        float4 v4 = (row < NN) ? *(const float4*)&x[(size_t)row * 128 + kc * 4]
                               : make_float4(0.f, 0.f, 0.f, 0.f);
        *(float4*)&sA[m * 128 + kc * 4] = v4;
    }
    __syncthreads();

    const int tx = tid & 15;   // 16 col-blocks of 8
    const int ty = tid >> 4;   // 16 row-blocks of 8

    ull acc[8][4];
#pragma unroll
    for (int r = 0; r < 8; r++)
#pragma unroll
        for (int c = 0; c < 4; c++) acc[r][c] = 0ull;

    const float* aBase = &sA[(ty * 8) * 128];
    const float* bBase = &sB[tx * 8];

#pragma unroll 4
    for (int k = 0; k < 128; k++) {
        ulonglong2 b01 = *(const ulonglong2*)(bBase + k * 128);
        ulonglong2 b23 = *(const ulonglong2*)(bBase + k * 128 + 4);
#pragma unroll
        for (int r = 0; r < 8; r++) {
            ull a2 = pk2(aBase[r * 128 + k]);   // LDS.32 broadcast
            fma2(acc[r][0], a2, b01.x);
            fma2(acc[r][1], a2, b01.y);
            fma2(acc[r][2], a2, b23.x);
            fma2(acc[r][3], a2, b23.y);
        }
    }

    float4 bi0 = *(const float4*)&sbias[tx * 8];
    float4 bi1 = *(const float4*)&sbias[tx * 8 + 4];
#pragma unroll
    for (int r = 0; r < 8; r++) {
        int row = row0 + ty * 8 + r;
        if (row < NN) {
            float2 p0 = up2(acc[r][0]), p1 = up2(acc[r][1]);
            float2 p2 = up2(acc[r][2]), p3 = up2(acc[r][3]);
            float4 o0 = make_float4(p0.x + bi0.x, p0.y + bi0.y,
                                    p1.x + bi0.z, p1.y + bi0.w);
            float4 o1 = make_float4(p2.x + bi1.x, p2.y + bi1.y,
                                    p3.x + bi1.z, p3.y + bi1.w);
            *(float4*)&dst[(size_t)row * 128 + tx * 8]     = o0;
            *(float4*)&dst[(size_t)row * 128 + tx * 8 + 4] = o1;
        }
    }
}

// ---------------------------------------------------------------------------
// K2: edge GEMM.  edge_attr = [cos(rel_t*wt+bt) | msg]  (built in smem),
//     g_e = edge_attr @ We.   Same GEMM core as K1, no bias.
// ---------------------------------------------------------------------------
#define EDGE_SMEM_FLOATS (128 * 128 * 2 + 128 + 64 + 64)
#define EDGE_SMEM_BYTES  (EDGE_SMEM_FLOATS * 4)

__global__ void __launch_bounds__(256, 1) edge_gemm_kernel(
    const int*   __restrict__ ei,          // [2*E]: src then dst
    const float* __restrict__ last_update,
    const float* __restrict__ t,
    const float* __restrict__ msg,
    const float* __restrict__ wt,
    const float* __restrict__ bt,
    const float* __restrict__ We)
{
    extern __shared__ float sm[];
    float* sA   = sm;                 // edge_attr tile [m][k] 128x128
    float* sB   = sm + 128 * 128;     // We tile        [k][n] 128x128
    float* srel = sB + 128 * 128;     // rel_t per edge  128
    float* swt  = srel + 128;         // 64
    float* sbt  = swt + 64;           // 64

    const int tid = threadIdx.x;
    const int e0  = blockIdx.x * 128;

    for (int idx = tid; idx < 128 * 32; idx += 256) {
        int k = idx >> 5, nc = idx & 31;
        *(float4*)&sB[k * 128 + nc * 4] = *(const float4*)&We[k * 128 + nc * 4];
    }
    if (tid < 64)            swt[tid]       = wt[tid];
    else if (tid < 128)      sbt[tid - 64]  = bt[tid - 64];
    if (tid < 128) {
        int edge = e0 + tid;
        float rv = 0.0f;
        if (edge < NE) {
            int s = ei[edge];
            rv = last_update[s] - t[edge];
        }
        srel[tid] = rv;
    }
    // msg half of edge_attr (does not depend on srel)
    for (int idx = tid; idx < 128 * 16; idx += 256) {
        int m = idx >> 4, kc = (idx & 15) * 4;
        int edge = e0 + m;
        float4 mv = (edge < NE) ? *(const float4*)&msg[(size_t)edge * 64 + kc]
                                : make_float4(0.f, 0.f, 0.f, 0.f);
        *(float4*)&sA[m * 128 + 64 + kc] = mv;
    }
    __syncthreads();

    // time-encoding half of edge_attr
    for (int idx = tid; idx < 128 * 16; idx += 256) {
        int m = idx >> 4, kc = (idx & 15) * 4;
        float rt = srel[m];
        float4 cv;
        cv.x = cos_arg(rt, swt[kc + 0], sbt[kc + 0]);
        cv.y = cos_arg(rt, swt[kc + 1], sbt[kc + 1]);
        cv.z = cos_arg(rt, swt[kc + 2], sbt[kc + 2]);
        cv.w = cos_arg(rt, swt[kc + 3], sbt[kc + 3]);
        *(float4*)&sA[m * 128 + kc] = cv;
    }
    __syncthreads();

    const int tx = tid & 15;
    const int ty = tid >> 4;

    ull acc[8][4];
#pragma unroll
    for (int r = 0; r < 8; r++)
#pragma unroll
        for (int c = 0; c < 4; c++) acc[r][c] = 0ull;

    const float* aBase = &sA[(ty * 8) * 128];
    const float* bBase = &sB[tx * 8];

#pragma unroll 4
    for (int k = 0; k < 128; k++) {
        ulonglong2 b01 = *(const ulonglong2*)(bBase + k * 128);
        ulonglong2 b23 = *(const ulonglong2*)(bBase + k * 128 + 4);
#pragma unroll
        for (int r = 0; r < 8; r++) {
            ull a2 = pk2(aBase[r * 128 + k]);
            fma2(acc[r][0], a2, b01.x);
            fma2(acc[r][1], a2, b01.y);
            fma2(acc[r][2], a2, b23.x);
            fma2(acc[r][3], a2, b23.y);
        }
    }

#pragma unroll
    for (int r = 0; r < 8; r++) {
        int edge = e0 + ty * 8 + r;
        if (edge < NE) {
            float2 p0 = up2(acc[r][0]), p1 = up2(acc[r][1]);
            float2 p2 = up2(acc[r][2]), p3 = up2(acc[r][3]);
            float4 o0 = make_float4(p0.x, p0.y, p1.x, p1.y);
            float4 o1 = make_float4(p2.x, p2.y, p3.x, p3.y);
            *(float4*)&g_e[(size_t)edge * 128 + tx * 8]     = o0;
            *(float4*)&g_e[(size_t)edge * 128 + tx * 8 + 4] = o1;
        }
    }
}

// ---------------------------------------------------------------------------
// K3: per-edge attention logits + segment max.  One warp per edge.
// alpha[e,h] = dot(q[dst], k[src]+e) / sqrt(64)
// ---------------------------------------------------------------------------
__global__ void __launch_bounds__(256) alpha_kernel(const int* __restrict__ ei)
{
    int edge = blockIdx.x * 8 + (threadIdx.x >> 5);
    int lane = threadIdx.x & 31;
    if (edge >= NE) return;
    int s = ei[edge];
    int d = ei[NE + edge];
    int c = lane * 4;                    // lanes 0-15: head 0, 16-31: head 1

    float4 qv = *(const float4*)&g_q[(size_t)d * 128 + c];
    float4 kv = *(const float4*)&g_k[(size_t)s * 128 + c];
    float4 ev = *(const float4*)&g_e[(size_t)edge * 128 + c];

    float p = qv.x * (kv.x + ev.x) + qv.y * (kv.y + ev.y)
            + qv.z * (kv.z + ev.z) + qv.w * (kv.w + ev.w);
    p += __shfl_xor_sync(0xffffffffu, p, 8);
    p += __shfl_xor_sync(0xffffffffu, p, 4);
    p += __shfl_xor_sync(0xffffffffu, p, 2);
    p += __shfl_xor_sync(0xffffffffu, p, 1);

    if ((lane & 15) == 0) {
        int h = lane >> 4;
        float alpha = p * 0.125f;        // 1/sqrt(64)
        g_ex[(size_t)edge * 2 + h] = alpha;
        atomicMax(&g_amax[d * 2 + h], fkey(alpha));
    }
}

// ---------------------------------------------------------------------------
// K4: ex = exp(alpha - amax[dst]); segment sum of ex.
// ---------------------------------------------------------------------------
__global__ void __launch_bounds__(256) expsum_kernel(const int* __restrict__ ei)
{
    int idx = blockIdx.x * blockDim.x + threadIdx.x;
    if (idx >= NE * 2) return;
    int edge = idx >> 1, h = idx & 1;
    int d = ei[NE + edge];
    float a  = g_ex[idx];
    float mx = funkey(g_amax[d * 2 + h]);
    float ex = expf(a - mx);
    g_ex[idx] = ex;
    atomicAdd(&g_denom[d * 2 + h], ex);
}

// ---------------------------------------------------------------------------
// K5: weighted scatter-add: out[dst] += attn * (v[src] + e).
// One warp per edge, 16-byte vector reductions (sm_90+ red.global.add.v4.f32).
// out already holds the skip connection from K1.
// ---------------------------------------------------------------------------
__global__ void __launch_bounds__(256) agg_kernel(const int* __restrict__ ei,
                                                  float* __restrict__ out)
{
    int edge = blockIdx.x * 8 + (threadIdx.x >> 5);
    int lane = threadIdx.x & 31;
    if (edge >= NE) return;
    int s = ei[edge];
    int d = ei[NE + edge];
    int h = lane >> 4;

    float ex   = g_ex[(size_t)edge * 2 + h];
    float den  = g_denom[d * 2 + h];
    float attn = ex / (den + 1e-16f);

    int c = lane * 4;
    float4 vv = *(const float4*)&g_v[(size_t)s * 128 + c];
    float4 ev = *(const float4*)&g_e[(size_t)edge * 128 + c];
    float4 r  = make_float4(attn * (vv.x + ev.x), attn * (vv.y + ev.y),
                            attn * (vv.z + ev.z), attn * (vv.w + ev.w));
    float* p = &out[(size_t)d * 128 + c];
    asm volatile("red.global.add.v4.f32 [%0], {%1, %2, %3, %4};"
                 :: "l"(p), "f"(r.x), "f"(r.y), "f"(r.z), "f"(r.w)
                 : "memory");
}

// ---------------------------------------------------------------------------
// kernel_launch
// ---------------------------------------------------------------------------
extern "C" void kernel_launch(void* const* d_in, const int* in_sizes, int n_in,
                              void* d_out, int out_size)
{
    const float* x           = (const float*)d_in[0];
    const float* last_update = (const float*)d_in[1];
    const int*   ei          = (const int*)  d_in[2];   // [2, E] int32
    const float* t           = (const float*)d_in[3];
    const float* msg         = (const float*)d_in[4];
    const float* wt          = (const float*)d_in[5];
    const float* bt          = (const float*)d_in[6];
    const float* Wq          = (const float*)d_in[7];
    const float* bq          = (const float*)d_in[8];
    const float* Wk          = (const float*)d_in[9];
    const float* bk          = (const float*)d_in[10];
    const float* Wv          = (const float*)d_in[11];
    const float* bv          = (const float*)d_in[12];
    const float* We          = (const float*)d_in[13];
    const float* Ws          = (const float*)d_in[14];
    const float* bs          = (const float*)d_in[15];
    float* out = (float*)d_out;

    cudaFuncSetAttribute(proj_kernel,
                         cudaFuncAttributeMaxDynamicSharedMemorySize,
                         PROJ_SMEM_BYTES);
    cudaFuncSetAttribute(edge_gemm_kernel,
                         cudaFuncAttributeMaxDynamicSharedMemorySize,
                         EDGE_SMEM_BYTES);

    init_kernel<<<(NN * 2 + 255) / 256, 256>>>();

    proj_kernel<<<dim3((NN + 127) / 128, 4), 256, PROJ_SMEM_BYTES>>>(
        x, Wq, bq, Wk, bk, Wv, bv, Ws, bs, out);

    edge_gemm_kernel<<<(NE + 127) / 128, 256, EDGE_SMEM_BYTES>>>(
        ei, last_update, t, msg, wt, bt, We);

    alpha_kernel<<<(NE + 7) / 8, 256>>>(ei);

    expsum_kernel<<<(NE * 2 + 255) / 256, 256>>>(ei);

    agg_kernel<<<(NE + 7) / 8, 256>>>(ei, out);
}

// round 8
// speedup vs baseline: 2.4731x; 2.4731x over previous
#include <cuda_runtime.h>
#include <math.h>
#include <stdint.h>

// Problem constants (fixed by the dataset)
#define NN 100000       // nodes
#define NE 600000       // edges
// IN = OUT = ED = 128, H = 2, C = 64, MSG = 64, T = 64

typedef unsigned long long ull;

// ---------------------------------------------------------------------------
// Scratch (device globals; no allocation allowed)
// ---------------------------------------------------------------------------
__device__ float    g_q[(size_t)NN * 128];
__device__ float    g_k[(size_t)NN * 128];
__device__ float    g_v[(size_t)NN * 128];
__device__ float    g_e[(size_t)NE * 128];
__device__ float    g_ex[(size_t)NE * 2];
__device__ unsigned g_amax[(size_t)NN * 2];
__device__ float    g_denom[(size_t)NN * 2];

// Pre-packed B fragments for mma.sync.m16n8k16 (row.col, bf16):
// [mat 0..4][term hi/lo][kstep 0..7][ntile 0..15][lane 0..31] -> uint2 {b0,b1}
// mat: 0=Wq 1=Wk 2=Wv 3=Wskip 4=We
__device__ __align__(16) uint2 g_bfrag[5 * 2 * 8 * 16 * 32];

// ---------------------------------------------------------------------------
// Helpers
// ---------------------------------------------------------------------------

// fp32 -> bf16 (round-to-nearest-even) of hi or residual-lo part
__device__ __forceinline__ unsigned bf16_rn(float x) {
    unsigned u = __float_as_uint(x);
    return (u + 0x7FFFu + ((u >> 16) & 1u)) >> 16;
}
__device__ __forceinline__ void bf16_split(float x, unsigned &hi, unsigned &lo) {
    hi = bf16_rn(x);
    float r = x - __uint_as_float(hi << 16);
    lo = bf16_rn(r);
}
// pack two floats' hi parts / lo parts into b16x2 words
__device__ __forceinline__ void split_pack2(float x0, float x1,
                                            unsigned &ph, unsigned &pl) {
    unsigned h0, l0, h1, l1;
    bf16_split(x0, h0, l0);
    bf16_split(x1, h1, l1);
    ph = h0 | (h1 << 16);
    pl = l0 | (l1 << 16);
}
// select hi(term=0) or lo(term=1) bf16 of x
__device__ __forceinline__ unsigned bf16_term(float x, int term) {
    unsigned h, l;
    bf16_split(x, h, l);
    return term ? l : h;
}

// Total-order float key for unsigned atomicMax
__device__ __forceinline__ unsigned fkey(float f) {
    unsigned u = __float_as_uint(f);
    return (u & 0x80000000u) ? ~u : (u | 0x80000000u);
}
__device__ __forceinline__ float funkey(unsigned k) {
    return (k & 0x80000000u) ? __uint_as_float(k & 0x7fffffffu)
                             : __uint_as_float(~k);
}

// cos(rel_t*w + b): reference's exact fp32 arg, fp32 Cody-Waite 2*pi reduction
__device__ __forceinline__ float cosx(float rt, float w, float b) {
    const float C1 = 6.2831854820251465f;     // float(2*pi)
    const float C2 = -1.7484551e-07f;         // 2*pi - C1
    float arg = __fadd_rn(__fmul_rn(rt, w), b);
    float k = rintf(arg * 0.15915494309189535f);
    float r = fmaf(-k, C1, arg);
    r = fmaf(-k, C2, r);
    return cosf(r);
}

// m16n8k16 bf16 mma, D += A*B (fp32 accum). Stable PTX ISA (sm_80+).
__device__ __forceinline__ void mma16816(float* d, const unsigned* a,
                                         const uint2 b) {
    asm volatile(
        "mma.sync.aligned.m16n8k16.row.col.f32.bf16.bf16.f32 "
        "{%0,%1,%2,%3}, {%4,%5,%6,%7}, {%8,%9}, {%0,%1,%2,%3};"
        : "+f"(d[0]), "+f"(d[1]), "+f"(d[2]), "+f"(d[3])
        : "r"(a[0]), "r"(a[1]), "r"(a[2]), "r"(a[3]), "r"(b.x), "r"(b.y));
}

// ---------------------------------------------------------------------------
// K0: init segment-softmax scratch
// ---------------------------------------------------------------------------
__global__ void init_kernel() {
    int i = blockIdx.x * blockDim.x + threadIdx.x;
    if (i < NN * 2) { g_amax[i] = 0u; g_denom[i] = 0.0f; }
}

// ---------------------------------------------------------------------------
// K-prep: pack all 5 weight matrices into B-fragment order.
// W is [K=128, N=128] row-major; B fragment (n8k16 col-major) for lane L:
//   g = L>>2 (n within ntile), tg = L&3 (k pairs)
//   b0 = { W[k0+tg*2][n], W[k0+tg*2+1][n] },  b1 = same with k+8
// ---------------------------------------------------------------------------
__global__ void prep_w_kernel(const float* __restrict__ Wq,
                              const float* __restrict__ Wk,
                              const float* __restrict__ Wv,
                              const float* __restrict__ Ws,
                              const float* __restrict__ We) {
    int gid = blockIdx.x * 256 + threadIdx.x;     // 5*2*8*16*32 = 40960
    if (gid >= 40960) return;
    int lane = gid & 31;
    int nt   = (gid >> 5) & 15;
    int ks   = (gid >> 9) & 7;
    int term = (gid >> 12) & 1;
    int mat  = gid >> 13;
    const float* W = (mat == 0) ? Wq : (mat == 1) ? Wk : (mat == 2) ? Wv
                   : (mat == 3) ? Ws : We;
    int g  = lane >> 2, tg = lane & 3;
    int n  = nt * 8 + g;
    int k0 = ks * 16 + tg * 2;
    unsigned b0 = bf16_term(W[k0 * 128 + n], term)
                | (bf16_term(W[(k0 + 1) * 128 + n], term) << 16);
    unsigned b1 = bf16_term(W[(k0 + 8) * 128 + n], term)
                | (bf16_term(W[(k0 + 9) * 128 + n], term) << 16);
    g_bfrag[gid] = make_uint2(b0, b1);
}

// ---------------------------------------------------------------------------
// GEMM core shared pieces
// A tiles live in smem as bf16 with row stride 136 (272B): conflict-free
// 4xLDS.32 fragment loads (word idx = row*68 + col/2).
// Warp tiling (8 warps, CTA 128x128): warp w -> rows (w&1)*64 + mt*16,
// cols (w>>1)*32 + nt*8; mt,nt in 0..3.
// ---------------------------------------------------------------------------
#define A_STRIDE_W 68                      // u32 words per A row
#define A_TILE_B   (128 * 136 * 2)         // 34816 bytes

// Load the 4-reg A fragment at (row0, kword0) from u32 smem image
__device__ __forceinline__ void lda_frag(unsigned* a, const unsigned* sA,
                                         int row0, int kw) {
    int base = row0 * A_STRIDE_W + kw;
    a[0] = sA[base];
    a[1] = sA[base + 8 * A_STRIDE_W];
    a[2] = sA[base + 4];
    a[3] = sA[base + 8 * A_STRIDE_W + 4];
}

// Run the 3-term 128x128x128 MMA for one output matrix; acc[4][4][4]
__device__ __forceinline__ void mma_tile(float acc[4][4][4],
                                         const unsigned* sAh,
                                         const unsigned* sAl,
                                         const uint2* __restrict__ fragH,
                                         const uint2* __restrict__ fragL,
                                         int mrow0, int gnt0, int lane) {
    int g = lane >> 2, tg = lane & 3;
#pragma unroll
    for (int kt = 0; kt < 8; kt++) {
        int kw = kt * 8 + tg;              // col/2 within row
        unsigned ah[4][4], al[4][4];
#pragma unroll
        for (int mt = 0; mt < 4; mt++) {
            int r0 = mrow0 + mt * 16 + g;
            lda_frag(ah[mt], sAh, r0, kw);
            lda_frag(al[mt], sAl, r0, kw);
        }
#pragma unroll
        for (int nt = 0; nt < 4; nt++) {
            int fi = (kt * 16 + gnt0 + nt) * 32 + lane;
            uint2 bh = fragH[fi];
            uint2 bl = fragL[fi];
#pragma unroll
            for (int mt = 0; mt < 4; mt++) {
                mma16816(acc[mt][nt], ah[mt], bh);
                mma16816(acc[mt][nt], ah[mt], bl);
                mma16816(acc[mt][nt], al[mt], bh);
            }
        }
    }
}

// ---------------------------------------------------------------------------
// K1: fused node projections (q, k, v, skip). One CTA = 128 node rows;
// A built once, 4 B phases from prepacked fragments.
// ---------------------------------------------------------------------------
#define NODE_OFF_BIAS 0
#define NODE_OFF_AH   2048
#define NODE_OFF_AL   (2048 + A_TILE_B)
#define NODE_SMEM     (2048 + 2 * A_TILE_B)    // 71680

__global__ void __launch_bounds__(256) node_gemm_kernel(
    const float* __restrict__ x,
    const float* __restrict__ bq, const float* __restrict__ bk,
    const float* __restrict__ bv, const float* __restrict__ bs,
    float* __restrict__ out)
{
    extern __shared__ char smem[];
    float*    sBias = (float*)(smem + NODE_OFF_BIAS);
    unsigned* sAh   = (unsigned*)(smem + NODE_OFF_AH);
    unsigned* sAl   = (unsigned*)(smem + NODE_OFF_AL);
    const int tid = threadIdx.x, wid = tid >> 5, lane = tid & 31;

    for (int j = tid; j < 512; j += 256) {
        const float* b = (j < 128) ? bq : (j < 256) ? bk : (j < 384) ? bv : bs;
        sBias[j] = b[j & 127];
    }

    // Build A (hi/lo split of x rows)
    {
        int row = tid >> 1;
        int kh  = (tid & 1) << 6;
        long grow = (long)blockIdx.x * 128 + row;
        bool ok = grow < NN;
        const float4* xr = (const float4*)&x[(size_t)(ok ? grow : 0) * 128 + kh];
#pragma unroll
        for (int c = 0; c < 64; c += 4) {
            float4 v = ok ? xr[c >> 2] : make_float4(0.f, 0.f, 0.f, 0.f);
            int w0 = row * A_STRIDE_W + ((kh + c) >> 1);
            unsigned ph, pl;
            split_pack2(v.x, v.y, ph, pl);
            sAh[w0] = ph;  sAl[w0] = pl;
            split_pack2(v.z, v.w, ph, pl);
            sAh[w0 + 1] = ph;  sAl[w0 + 1] = pl;
        }
    }
    __syncthreads();

    const int mrow0 = (wid & 1) * 64;
    const int ncol0 = (wid >> 1) * 32;
    const int gnt0  = ncol0 >> 3;
    const int g = lane >> 2, tg = lane & 3;

    for (int s = 0; s < 4; s++) {
        float acc[4][4][4];
#pragma unroll
        for (int mt = 0; mt < 4; mt++)
#pragma unroll
            for (int nt = 0; nt < 4; nt++)
#pragma unroll
                for (int r = 0; r < 4; r++) acc[mt][nt][r] = 0.0f;

        const uint2* fragH = &g_bfrag[(size_t)(s * 2 + 0) * 8 * 16 * 32];
        const uint2* fragL = &g_bfrag[(size_t)(s * 2 + 1) * 8 * 16 * 32];
        mma_tile(acc, sAh, sAl, fragH, fragL, mrow0, gnt0, lane);

        float* dst = (s == 0) ? g_q : (s == 1) ? g_k : (s == 2) ? g_v : out;
#pragma unroll
        for (int mt = 0; mt < 4; mt++) {
            long m0 = (long)blockIdx.x * 128 + mrow0 + mt * 16 + g;
#pragma unroll
            for (int nt = 0; nt < 4; nt++) {
                int col = ncol0 + nt * 8 + tg * 2;
                float b0 = sBias[s * 128 + col];
                float b1 = sBias[s * 128 + col + 1];
                if (m0 < NN) {
                    float2 o = make_float2(acc[mt][nt][0] + b0,
                                           acc[mt][nt][1] + b1);
                    *(float2*)&dst[(size_t)m0 * 128 + col] = o;
                }
                if (m0 + 8 < NN) {
                    float2 o = make_float2(acc[mt][nt][2] + b0,
                                           acc[mt][nt][3] + b1);
                    *(float2*)&dst[(size_t)(m0 + 8) * 128 + col] = o;
                }
            }
        }
    }
}

// ---------------------------------------------------------------------------
// K2: edge GEMM.  A = [cos(rel_t*wt+bt) | msg] built in split form;
// g_e = A @ We with We fragments prepacked (mat 4).
// ---------------------------------------------------------------------------
#define EDGE_OFF_WT  0
#define EDGE_OFF_BT  256
#define EDGE_OFF_AH  512
#define EDGE_OFF_AL  (512 + A_TILE_B)
#define EDGE_SMEM    (512 + 2 * A_TILE_B)      // 70144

__global__ void __launch_bounds__(256) edge_gemm_kernel(
    const int*   __restrict__ ei,
    const float* __restrict__ last_update,
    const float* __restrict__ tv,
    const float* __restrict__ msg,
    const float* __restrict__ wt,
    const float* __restrict__ bt)
{
    extern __shared__ char smem[];
    float*    swt = (float*)(smem + EDGE_OFF_WT);
    float*    sbt = (float*)(smem + EDGE_OFF_BT);
    unsigned* sAh = (unsigned*)(smem + EDGE_OFF_AH);
    unsigned* sAl = (unsigned*)(smem + EDGE_OFF_AL);
    const int tid = threadIdx.x, wid = tid >> 5, lane = tid & 31;

    if (tid < 64)       swt[tid] = wt[tid];
    else if (tid < 128) sbt[tid - 64] = bt[tid - 64];
    __syncthreads();

    // Build A: even threads cos half (cols 0..63), odd threads msg half
    {
        int row = tid >> 1;
        long e = (long)blockIdx.x * 128 + row;
        bool ok = e < NE;
        if ((tid & 1) == 0) {
            float rt = 0.0f;
            if (ok) {
                int s = ei[e];
                rt = last_update[s] - tv[e];
            }
#pragma unroll 8
            for (int c = 0; c < 64; c += 2) {
                float v0 = ok ? cosx(rt, swt[c],     sbt[c])     : 0.0f;
                float v1 = ok ? cosx(rt, swt[c + 1], sbt[c + 1]) : 0.0f;
                unsigned ph, pl;
                split_pack2(v0, v1, ph, pl);
                int w0 = row * A_STRIDE_W + (c >> 1);
                sAh[w0] = ph;  sAl[w0] = pl;
            }
        } else {
            const float4* mr = (const float4*)&msg[(size_t)(ok ? e : 0) * 64];
#pragma unroll
            for (int c = 0; c < 64; c += 4) {
                float4 v = ok ? mr[c >> 2] : make_float4(0.f, 0.f, 0.f, 0.f);
                int w0 = row * A_STRIDE_W + 32 + (c >> 1);
                unsigned ph, pl;
                split_pack2(v.x, v.y, ph, pl);
                sAh[w0] = ph;  sAl[w0] = pl;
                split_pack2(v.z, v.w, ph, pl);
                sAh[w0 + 1] = ph;  sAl[w0 + 1] = pl;
            }
        }
    }
    __syncthreads();

    const int mrow0 = (wid & 1) * 64;
    const int ncol0 = (wid >> 1) * 32;
    const int gnt0  = ncol0 >> 3;
    const int g = lane >> 2, tg = lane & 3;

    float acc[4][4][4];
#pragma unroll
    for (int mt = 0; mt < 4; mt++)
#pragma unroll
        for (int nt = 0; nt < 4; nt++)
#pragma unroll
            for (int r = 0; r < 4; r++) acc[mt][nt][r] = 0.0f;

    const uint2* fragH = &g_bfrag[(size_t)(4 * 2 + 0) * 8 * 16 * 32];
    const uint2* fragL = &g_bfrag[(size_t)(4 * 2 + 1) * 8 * 16 * 32];
    mma_tile(acc, sAh, sAl, fragH, fragL, mrow0, gnt0, lane);

#pragma unroll
    for (int mt = 0; mt < 4; mt++) {
        long m0 = (long)blockIdx.x * 128 + mrow0 + mt * 16 + g;
#pragma unroll
        for (int nt = 0; nt < 4; nt++) {
            int col = ncol0 + nt * 8 + tg * 2;
            if (m0 < NE)
                *(float2*)&g_e[(size_t)m0 * 128 + col] =
                    make_float2(acc[mt][nt][0], acc[mt][nt][1]);
            if (m0 + 8 < NE)
                *(float2*)&g_e[(size_t)(m0 + 8) * 128 + col] =
                    make_float2(acc[mt][nt][2], acc[mt][nt][3]);
        }
    }
}

// ---------------------------------------------------------------------------
// K3: per-edge attention logits + segment max (one warp per edge)
// ---------------------------------------------------------------------------
__global__ void __launch_bounds__(256) alpha_kernel(const int* __restrict__ ei)
{
    int edge = blockIdx.x * 8 + (threadIdx.x >> 5);
    int lane = threadIdx.x & 31;
    if (edge >= NE) return;
    int s = ei[edge];
    int d = ei[NE + edge];
    int c = lane * 4;

    float4 qv = *(const float4*)&g_q[(size_t)d * 128 + c];
    float4 kv = *(const float4*)&g_k[(size_t)s * 128 + c];
    float4 ev = *(const float4*)&g_e[(size_t)edge * 128 + c];

    float p = qv.x * (kv.x + ev.x) + qv.y * (kv.y + ev.y)
            + qv.z * (kv.z + ev.z) + qv.w * (kv.w + ev.w);
    p += __shfl_xor_sync(0xffffffffu, p, 8);
    p += __shfl_xor_sync(0xffffffffu, p, 4);
    p += __shfl_xor_sync(0xffffffffu, p, 2);
    p += __shfl_xor_sync(0xffffffffu, p, 1);

    if ((lane & 15) == 0) {
        int h = lane >> 4;
        float alpha = p * 0.125f;
        g_ex[(size_t)edge * 2 + h] = alpha;
        atomicMax(&g_amax[d * 2 + h], fkey(alpha));
    }
}

// ---------------------------------------------------------------------------
// K4: ex = exp(alpha - amax[dst]); segment sum
// ---------------------------------------------------------------------------
__global__ void __launch_bounds__(256) expsum_kernel(const int* __restrict__ ei)
{
    int idx = blockIdx.x * blockDim.x + threadIdx.x;
    if (idx >= NE * 2) return;
    int edge = idx >> 1, h = idx & 1;
    int d = ei[NE + edge];
    float a  = g_ex[idx];
    float mx = funkey(g_amax[d * 2 + h]);
    float ex = expf(a - mx);
    g_ex[idx] = ex;
    atomicAdd(&g_denom[d * 2 + h], ex);
}

// ---------------------------------------------------------------------------
// K5: weighted scatter-add: out[dst] += attn * (v[src] + e)
// ---------------------------------------------------------------------------
__global__ void __launch_bounds__(256) agg_kernel(const int* __restrict__ ei,
                                                  float* __restrict__ out)
{
    int edge = blockIdx.x * 8 + (threadIdx.x >> 5);
    int lane = threadIdx.x & 31;
    if (edge >= NE) return;
    int s = ei[edge];
    int d = ei[NE + edge];
    int h = lane >> 4;

    float ex   = g_ex[(size_t)edge * 2 + h];
    float den  = g_denom[d * 2 + h];
    float attn = ex / (den + 1e-16f);

    int c = lane * 4;
    float4 vv = *(const float4*)&g_v[(size_t)s * 128 + c];
    float4 ev = *(const float4*)&g_e[(size_t)edge * 128 + c];
    float4 r  = make_float4(attn * (vv.x + ev.x), attn * (vv.y + ev.y),
                            attn * (vv.z + ev.z), attn * (vv.w + ev.w));
    float* p = &out[(size_t)d * 128 + c];
    asm volatile("red.global.add.v4.f32 [%0], {%1, %2, %3, %4};"
                 :: "l"(p), "f"(r.x), "f"(r.y), "f"(r.z), "f"(r.w)
                 : "memory");
}

// ---------------------------------------------------------------------------
// kernel_launch
// ---------------------------------------------------------------------------
extern "C" void kernel_launch(void* const* d_in, const int* in_sizes, int n_in,
                              void* d_out, int out_size)
{
    const float* x           = (const float*)d_in[0];
    const float* last_update = (const float*)d_in[1];
    const int*   ei          = (const int*)  d_in[2];
    const float* t           = (const float*)d_in[3];
    const float* msg         = (const float*)d_in[4];
    const float* wt          = (const float*)d_in[5];
    const float* bt          = (const float*)d_in[6];
    const float* Wq          = (const float*)d_in[7];
    const float* bq          = (const float*)d_in[8];
    const float* Wk          = (const float*)d_in[9];
    const float* bk          = (const float*)d_in[10];
    const float* Wv          = (const float*)d_in[11];
    const float* bv          = (const float*)d_in[12];
    const float* We          = (const float*)d_in[13];
    const float* Ws          = (const float*)d_in[14];
    const float* bs          = (const float*)d_in[15];
    float* out = (float*)d_out;

    cudaFuncSetAttribute(node_gemm_kernel,
                         cudaFuncAttributeMaxDynamicSharedMemorySize, NODE_SMEM);
    cudaFuncSetAttribute(edge_gemm_kernel,
                         cudaFuncAttributeMaxDynamicSharedMemorySize, EDGE_SMEM);

    init_kernel<<<(NN * 2 + 255) / 256, 256>>>();
    prep_w_kernel<<<(40960 + 255) / 256, 256>>>(Wq, Wk, Wv, Ws, We);

    node_gemm_kernel<<<(NN + 127) / 128, 256, NODE_SMEM>>>(
        x, bq, bk, bv, bs, out);

    edge_gemm_kernel<<<(NE + 127) / 128, 256, EDGE_SMEM>>>(
        ei, last_update, t, msg, wt, bt);

    alpha_kernel<<<(NE + 7) / 8, 256>>>(ei);
    expsum_kernel<<<(NE * 2 + 255) / 256, 256>>>(ei);
    agg_kernel<<<(NE + 7) / 8, 256>>>(ei, out);
}